// round 14
// baseline (speedup 1.0000x reference)
#include <cuda_runtime.h>
#include <cuda_bf16.h>
#include <cstdint>

// Problem constants (fixed by the dataset)
#define NN 100000
#define EE 3200000
#define F0 256
#define HID 128
#define NCLS 64

// ---------------- scratch (static device globals; no allocation) ------------
__device__ __nv_bfloat16 g_hA16[(size_t)NN * HID];  // 25.6 MB (GEMM out, nsrc-prescaled)
__device__ __nv_bfloat16 g_hB16[(size_t)NN * HID];  // 25.6 MB (agg output)
__device__ int   g_csr[EE];                         // 12.8 MB
__device__ int   g_deg_in[NN];
__device__ int   g_deg_out[NN];
__device__ float g_nsrc[NN];
__device__ float g_ndst[NN];
__device__ int   g_rowptr[NN + 1];
__device__ int   g_wptr[NN];
__device__ int   g_incl[NN];
__device__ int   g_bsums[256];

// ---------------- graph preprocessing ---------------------------------------
__global__ void k_zero_deg() {
    int i = blockIdx.x * blockDim.x + threadIdx.x;
    if (i < NN) { g_deg_in[i] = 0; g_deg_out[i] = 0; }
}

// src/dst are int32 (JAX x64 disabled; astype(int64) is a no-op there).
__global__ void k_count(const int* __restrict__ src,
                        const int* __restrict__ dst) {
    int e = blockIdx.x * blockDim.x + threadIdx.x;
    if (e < EE) {
        atomicAdd(&g_deg_out[src[e]], 1);
        atomicAdd(&g_deg_in[dst[e]], 1);
    }
}

__global__ void k_scan1() {
    __shared__ int sh[256];
    const int tid = threadIdx.x;
    const int base = blockIdx.x * 1024 + tid * 4;
    int v0 = (base + 0 < NN) ? g_deg_in[base + 0] : 0;
    int v1 = (base + 1 < NN) ? g_deg_in[base + 1] : 0;
    int v2 = (base + 2 < NN) ? g_deg_in[base + 2] : 0;
    int v3 = (base + 3 < NN) ? g_deg_in[base + 3] : 0;
    int p0 = v0, p1 = p0 + v1, p2 = p1 + v2, p3 = p2 + v3;
    sh[tid] = p3;
    __syncthreads();
    for (int off = 1; off < 256; off <<= 1) {
        int t = (tid >= off) ? sh[tid - off] : 0;
        __syncthreads();
        sh[tid] += t;
        __syncthreads();
    }
    int toff = sh[tid] - p3;
    if (base + 0 < NN) g_incl[base + 0] = toff + p0;
    if (base + 1 < NN) g_incl[base + 1] = toff + p1;
    if (base + 2 < NN) g_incl[base + 2] = toff + p2;
    if (base + 3 < NN) g_incl[base + 3] = toff + p3;
    if (tid == 0) g_bsums[blockIdx.x] = sh[255];
}

__global__ void k_scan2(int nb) {
    __shared__ int sh[128];
    const int tid = threadIdx.x;
    sh[tid] = (tid < nb) ? g_bsums[tid] : 0;
    __syncthreads();
    for (int off = 1; off < 128; off <<= 1) {
        int t = (tid >= off) ? sh[tid - off] : 0;
        __syncthreads();
        sh[tid] += t;
        __syncthreads();
    }
    if (tid < nb) g_bsums[tid] = sh[tid];
}

// scan3 + norms fused: rowptr/wptr and both degree norms.
__global__ void k_scan3() {
    int i = blockIdx.x * blockDim.x + threadIdx.x;
    if (i < NN) {
        int blk = i >> 10;
        int off = (blk > 0) ? g_bsums[blk - 1] : 0;
        int di = g_deg_in[i];
        int excl = off + g_incl[i] - di;
        g_rowptr[i] = excl;
        g_wptr[i] = excl;
        int d_o = g_deg_out[i];
        g_nsrc[i] = rsqrtf((float)(d_o > 0 ? d_o : 1));
        g_ndst[i] = rsqrtf((float)(di > 0 ? di : 1));
    }
    if (i == 0) g_rowptr[NN] = EE;
}

__global__ void k_scatter(const int* __restrict__ src,
                          const int* __restrict__ dst) {
    int e = blockIdx.x * blockDim.x + threadIdx.x;
    if (e < EE) {
        int d = dst[e];
        int pos = atomicAdd(&g_wptr[d], 1);
        g_csr[pos] = src[e];
    }
}

// ---------------- tensor-core GEMM (bf16 HMMA): g_hA16 = nsrc .* (A @ B) ----
// BM=128, BN=NC (128 or 64), BK=32. 256 threads = 8 warps (4 in M x 2 in N).
// mma.sync.m16n8k16.bf16, fp32 accumulate. Operands staged as bf16x2 pairs in
// a permuted [plane][lane] shared layout (stride 33 -> conflict-free LDS.32).
// Epilogue pre-scales each output row by n_src[row] (row-linear: exact
// reassociation of the aggregation's per-edge scale).

__device__ __forceinline__ void mma_bf16(float* d, const uint32_t* a, const uint32_t* b) {
    asm volatile(
        "mma.sync.aligned.m16n8k16.row.col.f32.bf16.bf16.f32 "
        "{%0,%1,%2,%3}, {%4,%5,%6,%7}, {%8,%9}, {%0,%1,%2,%3};"
        : "+f"(d[0]), "+f"(d[1]), "+f"(d[2]), "+f"(d[3])
        : "r"(a[0]), "r"(a[1]), "r"(a[2]), "r"(a[3]), "r"(b[0]), "r"(b[1]));
}

template<bool FROM_X, int BN>
__global__ __launch_bounds__(256)
void k_gemm_bf(const float* __restrict__ xext,
               const float* __restrict__ Bsrc,
               int M, int K) {
    const float* __restrict__ Af = xext;
    const __nv_bfloat16* __restrict__ Ah = (const __nv_bfloat16*)g_hB16;
    __nv_bfloat16* __restrict__ C = g_hA16;
    constexpr int NC = BN;
    constexpr int BK = 32;
    constexpr int APITER = (128 * (BK / 2)) / 256;   // 8 bf16x2 pairs / thread
    constexpr int BPITER = ((BK / 2) * BN) / 256;    // 8 (BN=128) or 4 (BN=64)
    constexpr int NT = BN / 16;                      // n-tiles per warp

    __shared__ uint32_t AsU[64 * 33];
    __shared__ uint32_t BsU[(BN / 8) * 2 * 2 * 33];

    const int tid  = threadIdx.x;
    const int lane = tid & 31;
    const int w    = tid >> 5;
    const int warpM = w & 3;
    const int warpN = w >> 2;
    const int rowBase = blockIdx.x * 128;

    float acc[2][NT][4];
#pragma unroll
    for (int j = 0; j < 2; j++)
#pragma unroll
        for (int n = 0; n < NT; n++)
#pragma unroll
            for (int r = 0; r < 4; r++) acc[j][n][r] = 0.f;

    uint32_t sa[APITER];
    uint32_t sb[BPITER];

    auto loadAB = [&](int k0) {
#pragma unroll
        for (int i = 0; i < APITER; i++) {
            int pidx = i * 256 + tid;
            int m = pidx >> 4;
            int kp = pidx & 15;
            int grow = rowBase + m;
            if (FROM_X) {
                float2 f = (grow < M) ? *(const float2*)&Af[(size_t)grow * K + k0 + kp * 2]
                                      : make_float2(0.f, 0.f);
                __nv_bfloat162 h = __float22bfloat162_rn(f);
                sa[i] = *(uint32_t*)&h;
            } else {
                sa[i] = (grow < M) ? *(const uint32_t*)&Ah[(size_t)grow * K + k0 + kp * 2]
                                   : 0u;
            }
        }
#pragma unroll
        for (int i = 0; i < BPITER; i++) {
            int idx = i * 256 + tid;
            int n = idx % BN;
            int kp = idx / BN;
            float w0 = Bsrc[(size_t)(k0 + kp * 2) * NC + n];
            float w1 = Bsrc[(size_t)(k0 + kp * 2 + 1) * NC + n];
            __nv_bfloat162 h = __float22bfloat162_rn(make_float2(w0, w1));
            sb[i] = *(uint32_t*)&h;
        }
    };

    auto storeAB = [&]() {
#pragma unroll
        for (int i = 0; i < APITER; i++) {
            int pidx = i * 256 + tid;
            int m = pidx >> 4;
            int kp = pidx & 15;
            int mt = m >> 4, rr = m & 15;
            int ks = kp >> 3, j = kp & 7;
            int ln = ((rr & 7) << 2) | (j & 3);
            int reg = (rr >> 3) | (((j >> 2) & 1) << 1);
            int plane = ((mt << 1) | ks) * 4 + reg;
            AsU[plane * 33 + ln] = sa[i];
        }
#pragma unroll
        for (int i = 0; i < BPITER; i++) {
            int idx = i * 256 + tid;
            int n = idx % BN;
            int kp = idx / BN;
            int nt = n >> 3, nn = n & 7;
            int ks = kp >> 3, jj = kp & 7;
            int ln = (nn << 2) | (jj & 3);
            int reg = jj >> 2;
            int plane = ((nt << 1) | ks) * 2 + reg;
            BsU[plane * 33 + ln] = sb[i];
        }
    };

    const int nChunks = K / BK;
    loadAB(0);
    storeAB();
    __syncthreads();

    for (int c = 0; c < nChunks; c++) {
        if (c + 1 < nChunks) loadAB((c + 1) * BK);

#pragma unroll
        for (int ks = 0; ks < 2; ks++) {
            uint32_t a[2][4];
#pragma unroll
            for (int j = 0; j < 2; j++) {
                int mt = warpM * 2 + j;
                int pb = ((mt << 1) | ks) * 4;
#pragma unroll
                for (int r = 0; r < 4; r++)
                    a[j][r] = AsU[(pb + r) * 33 + lane];
            }
#pragma unroll
            for (int n = 0; n < NT; n++) {
                int ntg = warpN * NT + n;
                int pb = ((ntg << 1) | ks) * 2;
                uint32_t b[2];
                b[0] = BsU[pb * 33 + lane];
                b[1] = BsU[(pb + 1) * 33 + lane];
                mma_bf16(acc[0][n], a[0], b);
                mma_bf16(acc[1][n], a[1], b);
            }
        }
        __syncthreads();
        if (c + 1 < nChunks) {
            storeAB();
            __syncthreads();
        }
    }

    // epilogue: pre-scale by n_src[row], convert to bf16x2, store
    const int r0 = rowBase + warpM * 32;
#pragma unroll
    for (int j = 0; j < 2; j++) {
        int row = r0 + j * 16 + (lane >> 2);
        float ns0 = (row < M)     ? g_nsrc[row]     : 0.f;
        float ns1 = (row + 8 < M) ? g_nsrc[row + 8] : 0.f;
#pragma unroll
        for (int n = 0; n < NT; n++) {
            int col = warpN * (NT * 8) + n * 8 + (lane & 3) * 2;
            if (row < M) {
                __nv_bfloat162 o0 = __float22bfloat162_rn(
                    make_float2(acc[j][n][0] * ns0, acc[j][n][1] * ns0));
                *(uint32_t*)&C[(size_t)row * NC + col] = *(uint32_t*)&o0;
            }
            if (row + 8 < M) {
                __nv_bfloat162 o1 = __float22bfloat162_rn(
                    make_float2(acc[j][n][2] * ns1, acc[j][n][3] * ns1));
                *(uint32_t*)&C[(size_t)(row + 8) * NC + col] = *(uint32_t*)&o1;
            }
        }
    }
}

// ---------------- aggregation (bf16 in / bf16 out) --------------------------
// hB16[n] = bf16( n_dst[n] * sum_c hA16[c] + b )   (rows already nsrc-scaled)
// One warp per node. uint4/lane (8 bf16): 16 lanes per row -> 2 edges/load.
// CSR indices batched 32 at a time via one coalesced load + shfl.
__global__ void k_agg128(const float* __restrict__ bias) {
    const __nv_bfloat16* __restrict__ hin = (const __nv_bfloat16*)g_hA16;
    __nv_bfloat16* __restrict__ hout = g_hB16;
    int gt = blockIdx.x * blockDim.x + threadIdx.x;
    int node = gt >> 5;
    int lane = gt & 31;
    if (node >= NN) return;
    int s0 = g_rowptr[node], s1 = g_rowptr[node + 1];
    const int half = lane >> 4;          // which edge of the pair
    const int fo = (lane & 15) * 8;      // 8 bf16 feats per lane

    float acc[4][8];
#pragma unroll
    for (int i = 0; i < 4; i++)
#pragma unroll
        for (int f = 0; f < 8; f++) acc[i][f] = 0.f;

    int e = s0;
    // 32-edge chunks: one coalesced csr load, 16 row-load steps (2 edges each)
    for (; e + 32 <= s1; e += 32) {
        int myidx = g_csr[e + lane];
#pragma unroll
        for (int j = 0; j < 16; j++) {
            int c = __shfl_sync(0xFFFFFFFFu, myidx, j * 2 + half);
            uint4 r = *(const uint4*)&hin[(size_t)c * 128 + fo];
            float2 f0 = __bfloat1622float2(*(__nv_bfloat162*)&r.x);
            float2 f1 = __bfloat1622float2(*(__nv_bfloat162*)&r.y);
            float2 f2 = __bfloat1622float2(*(__nv_bfloat162*)&r.z);
            float2 f3 = __bfloat1622float2(*(__nv_bfloat162*)&r.w);
            float* a = acc[j & 3];
            a[0] += f0.x; a[1] += f0.y; a[2] += f1.x; a[3] += f1.y;
            a[4] += f2.x; a[5] += f2.y; a[6] += f3.x; a[7] += f3.y;
        }
    }
    // remainder: 2 edges per step
    for (; e + 1 < s1; e += 2) {
        int c = g_csr[e + half];
        uint4 r = *(const uint4*)&hin[(size_t)c * 128 + fo];
        float2 f0 = __bfloat1622float2(*(__nv_bfloat162*)&r.x);
        float2 f1 = __bfloat1622float2(*(__nv_bfloat162*)&r.y);
        float2 f2 = __bfloat1622float2(*(__nv_bfloat162*)&r.z);
        float2 f3 = __bfloat1622float2(*(__nv_bfloat162*)&r.w);
        acc[0][0] += f0.x; acc[0][1] += f0.y; acc[0][2] += f1.x; acc[0][3] += f1.y;
        acc[0][4] += f2.x; acc[0][5] += f2.y; acc[0][6] += f3.x; acc[0][7] += f3.y;
    }
    if (e < s1 && half == 0) {           // odd tail: half 0 lanes only
        int c = g_csr[e];
        uint4 r = *(const uint4*)&hin[(size_t)c * 128 + fo];
        float2 f0 = __bfloat1622float2(*(__nv_bfloat162*)&r.x);
        float2 f1 = __bfloat1622float2(*(__nv_bfloat162*)&r.y);
        float2 f2 = __bfloat1622float2(*(__nv_bfloat162*)&r.z);
        float2 f3 = __bfloat1622float2(*(__nv_bfloat162*)&r.w);
        acc[1][0] += f0.x; acc[1][1] += f0.y; acc[1][2] += f1.x; acc[1][3] += f1.y;
        acc[1][4] += f2.x; acc[1][5] += f2.y; acc[1][6] += f3.x; acc[1][7] += f3.y;
    }

    float tot[8];
#pragma unroll
    for (int f = 0; f < 8; f++) {
        tot[f] = (acc[0][f] + acc[1][f]) + (acc[2][f] + acc[3][f]);
        tot[f] += __shfl_xor_sync(0xFFFFFFFFu, tot[f], 16);
    }

    if (half == 0) {
        float nd = g_ndst[node];
        float4 b0 = *(const float4*)&bias[fo];
        float4 b1 = *(const float4*)&bias[fo + 4];
        __nv_bfloat162 p0 = __float22bfloat162_rn(make_float2(tot[0] * nd + b0.x, tot[1] * nd + b0.y));
        __nv_bfloat162 p1 = __float22bfloat162_rn(make_float2(tot[2] * nd + b0.z, tot[3] * nd + b0.w));
        __nv_bfloat162 p2 = __float22bfloat162_rn(make_float2(tot[4] * nd + b1.x, tot[5] * nd + b1.y));
        __nv_bfloat162 p3 = __float22bfloat162_rn(make_float2(tot[6] * nd + b1.z, tot[7] * nd + b1.w));
        uint4 o;
        o.x = *(uint32_t*)&p0; o.y = *(uint32_t*)&p1;
        o.z = *(uint32_t*)&p2; o.w = *(uint32_t*)&p3;
        *(uint4*)&hout[(size_t)node * 128 + fo] = o;
    }
}

// Final layer: 64 bf16 feats = 128 B/row; 8 lanes per edge -> 4 edges/load.
__global__ void k_agg64_softmax(float* __restrict__ out,
                                const float* __restrict__ bias) {
    const __nv_bfloat16* __restrict__ hin = (const __nv_bfloat16*)g_hA16;
    int gt = blockIdx.x * blockDim.x + threadIdx.x;
    int node = gt >> 5;
    int lane = gt & 31;
    if (node >= NN) return;
    int s0 = g_rowptr[node], s1 = g_rowptr[node + 1];
    const int quarter = lane >> 3;        // which edge of the quad
    const int fo = (lane & 7) * 8;        // 8 bf16 feats per lane

    float acc[4][8];
#pragma unroll
    for (int i = 0; i < 4; i++)
#pragma unroll
        for (int f = 0; f < 8; f++) acc[i][f] = 0.f;

    int e = s0;
    for (; e + 32 <= s1; e += 32) {
        int myidx = g_csr[e + lane];
#pragma unroll
        for (int j = 0; j < 8; j++) {
            int c = __shfl_sync(0xFFFFFFFFu, myidx, j * 4 + quarter);
            uint4 r = *(const uint4*)&hin[(size_t)c * 64 + fo];
            float2 f0 = __bfloat1622float2(*(__nv_bfloat162*)&r.x);
            float2 f1 = __bfloat1622float2(*(__nv_bfloat162*)&r.y);
            float2 f2 = __bfloat1622float2(*(__nv_bfloat162*)&r.z);
            float2 f3 = __bfloat1622float2(*(__nv_bfloat162*)&r.w);
            float* a = acc[j & 3];
            a[0] += f0.x; a[1] += f0.y; a[2] += f1.x; a[3] += f1.y;
            a[4] += f2.x; a[5] += f2.y; a[6] += f3.x; a[7] += f3.y;
        }
    }
    for (; e + 3 < s1; e += 4) {
        int c = g_csr[e + quarter];
        uint4 r = *(const uint4*)&hin[(size_t)c * 64 + fo];
        float2 f0 = __bfloat1622float2(*(__nv_bfloat162*)&r.x);
        float2 f1 = __bfloat1622float2(*(__nv_bfloat162*)&r.y);
        float2 f2 = __bfloat1622float2(*(__nv_bfloat162*)&r.z);
        float2 f3 = __bfloat1622float2(*(__nv_bfloat162*)&r.w);
        acc[0][0] += f0.x; acc[0][1] += f0.y; acc[0][2] += f1.x; acc[0][3] += f1.y;
        acc[0][4] += f2.x; acc[0][5] += f2.y; acc[0][6] += f3.x; acc[0][7] += f3.y;
    }
    if (e < s1) {                          // 1..3 remaining edges
        int rem = s1 - e;
        if (quarter < rem) {
            int c = g_csr[e + quarter];
            uint4 r = *(const uint4*)&hin[(size_t)c * 64 + fo];
            float2 f0 = __bfloat1622float2(*(__nv_bfloat162*)&r.x);
            float2 f1 = __bfloat1622float2(*(__nv_bfloat162*)&r.y);
            float2 f2 = __bfloat1622float2(*(__nv_bfloat162*)&r.z);
            float2 f3 = __bfloat1622float2(*(__nv_bfloat162*)&r.w);
            acc[1][0] += f0.x; acc[1][1] += f0.y; acc[1][2] += f1.x; acc[1][3] += f1.y;
            acc[1][4] += f2.x; acc[1][5] += f2.y; acc[1][6] += f3.x; acc[1][7] += f3.y;
        }
    }

    float v[8];
    float nd = g_ndst[node];
#pragma unroll
    for (int f = 0; f < 8; f++) {
        float t = (acc[0][f] + acc[1][f]) + (acc[2][f] + acc[3][f]);
        t += __shfl_xor_sync(0xFFFFFFFFu, t, 8);
        t += __shfl_xor_sync(0xFFFFFFFFu, t, 16);
        v[f] = t * nd + bias[fo + f];
    }

    // softmax over 64 vals = 8 lanes (lane&7 groups) x 8 local
    float m = v[0];
#pragma unroll
    for (int f = 1; f < 8; f++) m = fmaxf(m, v[f]);
#pragma unroll
    for (int off = 4; off > 0; off >>= 1)
        m = fmaxf(m, __shfl_xor_sync(0xFFFFFFFFu, m, off));
    float s = 0.f;
    float ev[8];
#pragma unroll
    for (int f = 0; f < 8; f++) { ev[f] = __expf(v[f] - m); s += ev[f]; }
#pragma unroll
    for (int off = 4; off > 0; off >>= 1)
        s += __shfl_xor_sync(0xFFFFFFFFu, s, off);
    float inv = 1.0f / s;

    if (quarter == 0) {                    // lanes 0..7 write 8 fp32 each
        float4 o0 = make_float4(ev[0] * inv, ev[1] * inv, ev[2] * inv, ev[3] * inv);
        float4 o1 = make_float4(ev[4] * inv, ev[5] * inv, ev[6] * inv, ev[7] * inv);
        *(float4*)&out[(size_t)node * 64 + fo] = o0;
        *(float4*)&out[(size_t)node * 64 + fo + 4] = o1;
    }
}

// ---------------- launch -----------------------------------------------------
extern "C" void kernel_launch(void* const* d_in, const int* in_sizes, int n_in,
                              void* d_out, int out_size) {
    const float* x   = (const float*)d_in[0];
    const int*   src = (const int*)d_in[1];    // int32: JAX x64 disabled
    const int*   dst = (const int*)d_in[2];
    const float* W0  = (const float*)d_in[3];
    const float* b0  = (const float*)d_in[4];
    const float* W1  = (const float*)d_in[5];
    const float* b1  = (const float*)d_in[6];
    const float* W2  = (const float*)d_in[7];
    const float* b2  = (const float*)d_in[8];
    float* out = (float*)d_out;

    const int nblk = (NN + 255) / 256;
    const int eblk = (EE + 255) / 256;
    const int sblk = (NN + 1023) / 1024;   // 98

    // graph preprocessing
    k_zero_deg<<<nblk, 256>>>();
    k_count<<<eblk, 256>>>(src, dst);
    k_scan1<<<sblk, 256>>>();
    k_scan2<<<1, 128>>>(sblk);
    k_scan3<<<nblk, 256>>>();
    k_scatter<<<eblk, 256>>>(src, dst);

    const int aggblk  = (NN * 32 + 255) / 256;   // 12500
    const int gemmblk = (NN + 127) / 128;        // 782

    // layer 0: x @ W0 -> hA16 (nsrc-scaled) ; aggregate -> hB16
    k_gemm_bf<true, HID><<<gemmblk, 256>>>(x, W0, NN, F0);
    k_agg128<<<aggblk, 256>>>(b0);
    // layer 1: hB16 @ W1 -> hA16 ; aggregate -> hB16
    k_gemm_bf<false, HID><<<gemmblk, 256>>>(nullptr, W1, NN, HID);
    k_agg128<<<aggblk, 256>>>(b1);
    // layer 2: hB16 @ W2 -> hA16 ; aggregate + softmax -> out
    k_gemm_bf<false, NCLS><<<gemmblk, 256>>>(nullptr, W2, NN, HID);
    k_agg64_softmax<<<aggblk, 256>>>(out, b2);
}

// round 15
// speedup vs baseline: 1.1390x; 1.1390x over previous
#include <cuda_runtime.h>
#include <cuda_bf16.h>
#include <cstdint>

// Problem constants (fixed by the dataset)
#define NN 100000
#define EE 3200000
#define F0 256
#define HID 128
#define NCLS 64

// ---------------- scratch (static device globals; no allocation) ------------
__device__ __nv_bfloat16 g_hA16[(size_t)NN * HID];  // 25.6 MB (GEMM out, nsrc-prescaled)
__device__ __nv_bfloat16 g_hB16[(size_t)NN * HID];  // 25.6 MB (agg output)
__device__ int   g_csr[EE];                         // 12.8 MB
__device__ int   g_deg_in[NN];
__device__ int   g_deg_out[NN];
__device__ float g_nsrc[NN];
__device__ float g_ndst[NN];
__device__ int   g_rowptr[NN + 1];
__device__ int   g_wptr[NN];
__device__ int   g_incl[NN];
__device__ int   g_bsums[256];

// ---------------- graph preprocessing ---------------------------------------
__global__ void k_zero_deg() {
    int i = blockIdx.x * blockDim.x + threadIdx.x;
    if (i < NN) { g_deg_in[i] = 0; g_deg_out[i] = 0; }
}

// src/dst are int32 (JAX x64 disabled; astype(int64) is a no-op there).
__global__ void k_count(const int* __restrict__ src,
                        const int* __restrict__ dst) {
    int e = blockIdx.x * blockDim.x + threadIdx.x;
    if (e < EE) {
        atomicAdd(&g_deg_out[src[e]], 1);
        atomicAdd(&g_deg_in[dst[e]], 1);
    }
}

__global__ void k_scan1() {
    __shared__ int sh[256];
    const int tid = threadIdx.x;
    const int base = blockIdx.x * 1024 + tid * 4;
    int v0 = (base + 0 < NN) ? g_deg_in[base + 0] : 0;
    int v1 = (base + 1 < NN) ? g_deg_in[base + 1] : 0;
    int v2 = (base + 2 < NN) ? g_deg_in[base + 2] : 0;
    int v3 = (base + 3 < NN) ? g_deg_in[base + 3] : 0;
    int p0 = v0, p1 = p0 + v1, p2 = p1 + v2, p3 = p2 + v3;
    sh[tid] = p3;
    __syncthreads();
    for (int off = 1; off < 256; off <<= 1) {
        int t = (tid >= off) ? sh[tid - off] : 0;
        __syncthreads();
        sh[tid] += t;
        __syncthreads();
    }
    int toff = sh[tid] - p3;
    if (base + 0 < NN) g_incl[base + 0] = toff + p0;
    if (base + 1 < NN) g_incl[base + 1] = toff + p1;
    if (base + 2 < NN) g_incl[base + 2] = toff + p2;
    if (base + 3 < NN) g_incl[base + 3] = toff + p3;
    if (tid == 0) g_bsums[blockIdx.x] = sh[255];
}

__global__ void k_scan2(int nb) {
    __shared__ int sh[128];
    const int tid = threadIdx.x;
    sh[tid] = (tid < nb) ? g_bsums[tid] : 0;
    __syncthreads();
    for (int off = 1; off < 128; off <<= 1) {
        int t = (tid >= off) ? sh[tid - off] : 0;
        __syncthreads();
        sh[tid] += t;
        __syncthreads();
    }
    if (tid < nb) g_bsums[tid] = sh[tid];
}

// scan3 + norms fused: rowptr/wptr and both degree norms.
__global__ void k_scan3() {
    int i = blockIdx.x * blockDim.x + threadIdx.x;
    if (i < NN) {
        int blk = i >> 10;
        int off = (blk > 0) ? g_bsums[blk - 1] : 0;
        int di = g_deg_in[i];
        int excl = off + g_incl[i] - di;
        g_rowptr[i] = excl;
        g_wptr[i] = excl;
        int d_o = g_deg_out[i];
        g_nsrc[i] = rsqrtf((float)(d_o > 0 ? d_o : 1));
        g_ndst[i] = rsqrtf((float)(di > 0 ? di : 1));
    }
    if (i == 0) g_rowptr[NN] = EE;
}

__global__ void k_scatter(const int* __restrict__ src,
                          const int* __restrict__ dst) {
    int e = blockIdx.x * blockDim.x + threadIdx.x;
    if (e < EE) {
        int d = dst[e];
        int pos = atomicAdd(&g_wptr[d], 1);
        g_csr[pos] = src[e];
    }
}

// ---------------- tensor-core GEMM (bf16 HMMA): g_hA16 = nsrc .* (A @ B) ----
// BM=128, BN=NC (128 or 64), BK=32. 256 threads = 8 warps (4 in M x 2 in N).
// mma.sync.m16n8k16.bf16, fp32 accumulate. Operands staged as bf16x2 pairs in
// a permuted [plane][lane] shared layout (stride 33 -> conflict-free LDS.32).
// Epilogue pre-scales each output row by n_src[row] (row-linear: exact
// reassociation of the aggregation's per-edge scale).

__device__ __forceinline__ void mma_bf16(float* d, const uint32_t* a, const uint32_t* b) {
    asm volatile(
        "mma.sync.aligned.m16n8k16.row.col.f32.bf16.bf16.f32 "
        "{%0,%1,%2,%3}, {%4,%5,%6,%7}, {%8,%9}, {%0,%1,%2,%3};"
        : "+f"(d[0]), "+f"(d[1]), "+f"(d[2]), "+f"(d[3])
        : "r"(a[0]), "r"(a[1]), "r"(a[2]), "r"(a[3]), "r"(b[0]), "r"(b[1]));
}

template<bool FROM_X, int BN>
__global__ __launch_bounds__(256)
void k_gemm_bf(const float* __restrict__ xext,
               const float* __restrict__ Bsrc,
               int M, int K) {
    const float* __restrict__ Af = xext;
    const __nv_bfloat16* __restrict__ Ah = (const __nv_bfloat16*)g_hB16;
    __nv_bfloat16* __restrict__ C = g_hA16;
    constexpr int NC = BN;
    constexpr int BK = 32;
    constexpr int APITER = (128 * (BK / 2)) / 256;   // 8 bf16x2 pairs / thread
    constexpr int BPITER = ((BK / 2) * BN) / 256;    // 8 (BN=128) or 4 (BN=64)
    constexpr int NT = BN / 16;                      // n-tiles per warp

    __shared__ uint32_t AsU[64 * 33];
    __shared__ uint32_t BsU[(BN / 8) * 2 * 2 * 33];

    const int tid  = threadIdx.x;
    const int lane = tid & 31;
    const int w    = tid >> 5;
    const int warpM = w & 3;
    const int warpN = w >> 2;
    const int rowBase = blockIdx.x * 128;

    float acc[2][NT][4];
#pragma unroll
    for (int j = 0; j < 2; j++)
#pragma unroll
        for (int n = 0; n < NT; n++)
#pragma unroll
            for (int r = 0; r < 4; r++) acc[j][n][r] = 0.f;

    uint32_t sa[APITER];
    uint32_t sb[BPITER];

    auto loadAB = [&](int k0) {
#pragma unroll
        for (int i = 0; i < APITER; i++) {
            int pidx = i * 256 + tid;
            int m = pidx >> 4;
            int kp = pidx & 15;
            int grow = rowBase + m;
            if (FROM_X) {
                float2 f = (grow < M) ? *(const float2*)&Af[(size_t)grow * K + k0 + kp * 2]
                                      : make_float2(0.f, 0.f);
                __nv_bfloat162 h = __float22bfloat162_rn(f);
                sa[i] = *(uint32_t*)&h;
            } else {
                sa[i] = (grow < M) ? *(const uint32_t*)&Ah[(size_t)grow * K + k0 + kp * 2]
                                   : 0u;
            }
        }
#pragma unroll
        for (int i = 0; i < BPITER; i++) {
            int idx = i * 256 + tid;
            int n = idx % BN;
            int kp = idx / BN;
            float w0 = Bsrc[(size_t)(k0 + kp * 2) * NC + n];
            float w1 = Bsrc[(size_t)(k0 + kp * 2 + 1) * NC + n];
            __nv_bfloat162 h = __float22bfloat162_rn(make_float2(w0, w1));
            sb[i] = *(uint32_t*)&h;
        }
    };

    auto storeAB = [&]() {
#pragma unroll
        for (int i = 0; i < APITER; i++) {
            int pidx = i * 256 + tid;
            int m = pidx >> 4;
            int kp = pidx & 15;
            int mt = m >> 4, rr = m & 15;
            int ks = kp >> 3, j = kp & 7;
            int ln = ((rr & 7) << 2) | (j & 3);
            int reg = (rr >> 3) | (((j >> 2) & 1) << 1);
            int plane = ((mt << 1) | ks) * 4 + reg;
            AsU[plane * 33 + ln] = sa[i];
        }
#pragma unroll
        for (int i = 0; i < BPITER; i++) {
            int idx = i * 256 + tid;
            int n = idx % BN;
            int kp = idx / BN;
            int nt = n >> 3, nn = n & 7;
            int ks = kp >> 3, jj = kp & 7;
            int ln = (nn << 2) | (jj & 3);
            int reg = jj >> 2;
            int plane = ((nt << 1) | ks) * 2 + reg;
            BsU[plane * 33 + ln] = sb[i];
        }
    };

    const int nChunks = K / BK;
    loadAB(0);
    storeAB();
    __syncthreads();

    for (int c = 0; c < nChunks; c++) {
        if (c + 1 < nChunks) loadAB((c + 1) * BK);

#pragma unroll
        for (int ks = 0; ks < 2; ks++) {
            uint32_t a[2][4];
#pragma unroll
            for (int j = 0; j < 2; j++) {
                int mt = warpM * 2 + j;
                int pb = ((mt << 1) | ks) * 4;
#pragma unroll
                for (int r = 0; r < 4; r++)
                    a[j][r] = AsU[(pb + r) * 33 + lane];
            }
#pragma unroll
            for (int n = 0; n < NT; n++) {
                int ntg = warpN * NT + n;
                int pb = ((ntg << 1) | ks) * 2;
                uint32_t b[2];
                b[0] = BsU[pb * 33 + lane];
                b[1] = BsU[(pb + 1) * 33 + lane];
                mma_bf16(acc[0][n], a[0], b);
                mma_bf16(acc[1][n], a[1], b);
            }
        }
        __syncthreads();
        if (c + 1 < nChunks) {
            storeAB();
            __syncthreads();
        }
    }

    // epilogue: pre-scale by n_src[row], convert to bf16x2, store
    const int r0 = rowBase + warpM * 32;
#pragma unroll
    for (int j = 0; j < 2; j++) {
        int row = r0 + j * 16 + (lane >> 2);
        float ns0 = (row < M)     ? g_nsrc[row]     : 0.f;
        float ns1 = (row + 8 < M) ? g_nsrc[row + 8] : 0.f;
#pragma unroll
        for (int n = 0; n < NT; n++) {
            int col = warpN * (NT * 8) + n * 8 + (lane & 3) * 2;
            if (row < M) {
                __nv_bfloat162 o0 = __float22bfloat162_rn(
                    make_float2(acc[j][n][0] * ns0, acc[j][n][1] * ns0));
                *(uint32_t*)&C[(size_t)row * NC + col] = *(uint32_t*)&o0;
            }
            if (row + 8 < M) {
                __nv_bfloat162 o1 = __float22bfloat162_rn(
                    make_float2(acc[j][n][2] * ns1, acc[j][n][3] * ns1));
                *(uint32_t*)&C[(size_t)(row + 8) * NC + col] = *(uint32_t*)&o1;
            }
        }
    }
}

// ---------------- aggregation (bf16 in / bf16 out) --------------------------
// hB16[n] = bf16( n_dst[n] * sum_c hA16[c] + b )   (rows already nsrc-scaled)
// Round-10 proven structure: one warp per node, uint4/lane (8 bf16) so 16
// lanes cover a 128-feat row -> 2 edges per load, 8 edges in flight per iter,
// direct per-step CSR loads (no shfl), 4 independent accumulator banks.
__global__ void k_agg128(const float* __restrict__ bias) {
    const __nv_bfloat16* __restrict__ hin = (const __nv_bfloat16*)g_hA16;
    __nv_bfloat16* __restrict__ hout = g_hB16;
    int gt = blockIdx.x * blockDim.x + threadIdx.x;
    int node = gt >> 5;
    int lane = gt & 31;
    if (node >= NN) return;
    int s0 = g_rowptr[node], s1 = g_rowptr[node + 1];
    const int half = lane >> 4;          // which edge of the pair
    const int fo = (lane & 15) * 8;      // 8 bf16 feats per lane

    float acc[4][8];
#pragma unroll
    for (int i = 0; i < 4; i++)
#pragma unroll
        for (int f = 0; f < 8; f++) acc[i][f] = 0.f;

    int e = s0;
    for (; e + 7 < s1; e += 8) {
#pragma unroll
        for (int i = 0; i < 4; i++) {
            int c = g_csr[e + 2 * i + half];
            uint4 r = *(const uint4*)&hin[(size_t)c * 128 + fo];
            float2 f0 = __bfloat1622float2(*(__nv_bfloat162*)&r.x);
            float2 f1 = __bfloat1622float2(*(__nv_bfloat162*)&r.y);
            float2 f2 = __bfloat1622float2(*(__nv_bfloat162*)&r.z);
            float2 f3 = __bfloat1622float2(*(__nv_bfloat162*)&r.w);
            acc[i][0] += f0.x; acc[i][1] += f0.y;
            acc[i][2] += f1.x; acc[i][3] += f1.y;
            acc[i][4] += f2.x; acc[i][5] += f2.y;
            acc[i][6] += f3.x; acc[i][7] += f3.y;
        }
    }
    for (; e + 1 < s1; e += 2) {
        int c = g_csr[e + half];
        uint4 r = *(const uint4*)&hin[(size_t)c * 128 + fo];
        float2 f0 = __bfloat1622float2(*(__nv_bfloat162*)&r.x);
        float2 f1 = __bfloat1622float2(*(__nv_bfloat162*)&r.y);
        float2 f2 = __bfloat1622float2(*(__nv_bfloat162*)&r.z);
        float2 f3 = __bfloat1622float2(*(__nv_bfloat162*)&r.w);
        acc[0][0] += f0.x; acc[0][1] += f0.y;
        acc[0][2] += f1.x; acc[0][3] += f1.y;
        acc[0][4] += f2.x; acc[0][5] += f2.y;
        acc[0][6] += f3.x; acc[0][7] += f3.y;
    }
    if (e < s1 && half == 0) {           // odd tail: half-0 lanes only
        int c = g_csr[e];
        uint4 r = *(const uint4*)&hin[(size_t)c * 128 + fo];
        float2 f0 = __bfloat1622float2(*(__nv_bfloat162*)&r.x);
        float2 f1 = __bfloat1622float2(*(__nv_bfloat162*)&r.y);
        float2 f2 = __bfloat1622float2(*(__nv_bfloat162*)&r.z);
        float2 f3 = __bfloat1622float2(*(__nv_bfloat162*)&r.w);
        acc[1][0] += f0.x; acc[1][1] += f0.y;
        acc[1][2] += f1.x; acc[1][3] += f1.y;
        acc[1][4] += f2.x; acc[1][5] += f2.y;
        acc[1][6] += f3.x; acc[1][7] += f3.y;
    }

    float tot[8];
#pragma unroll
    for (int f = 0; f < 8; f++) {
        tot[f] = (acc[0][f] + acc[1][f]) + (acc[2][f] + acc[3][f]);
        tot[f] += __shfl_xor_sync(0xFFFFFFFFu, tot[f], 16);
    }

    if (half == 0) {
        float nd = g_ndst[node];
        float4 b0 = *(const float4*)&bias[fo];
        float4 b1 = *(const float4*)&bias[fo + 4];
        __nv_bfloat162 p0 = __float22bfloat162_rn(make_float2(tot[0] * nd + b0.x, tot[1] * nd + b0.y));
        __nv_bfloat162 p1 = __float22bfloat162_rn(make_float2(tot[2] * nd + b0.z, tot[3] * nd + b0.w));
        __nv_bfloat162 p2 = __float22bfloat162_rn(make_float2(tot[4] * nd + b1.x, tot[5] * nd + b1.y));
        __nv_bfloat162 p3 = __float22bfloat162_rn(make_float2(tot[6] * nd + b1.z, tot[7] * nd + b1.w));
        uint4 o;
        o.x = *(uint32_t*)&p0; o.y = *(uint32_t*)&p1;
        o.z = *(uint32_t*)&p2; o.w = *(uint32_t*)&p3;
        *(uint4*)&hout[(size_t)node * 128 + fo] = o;
    }
}

// Final layer: 64 bf16 feats = 128 B/row; 8 lanes per edge -> 4 edges/load.
__global__ void k_agg64_softmax(float* __restrict__ out,
                                const float* __restrict__ bias) {
    const __nv_bfloat16* __restrict__ hin = (const __nv_bfloat16*)g_hA16;
    int gt = blockIdx.x * blockDim.x + threadIdx.x;
    int node = gt >> 5;
    int lane = gt & 31;
    if (node >= NN) return;
    int s0 = g_rowptr[node], s1 = g_rowptr[node + 1];
    const int quarter = lane >> 3;        // which edge of the quad
    const int fo = (lane & 7) * 8;        // 8 bf16 feats per lane

    float acc[2][8];
#pragma unroll
    for (int i = 0; i < 2; i++)
#pragma unroll
        for (int f = 0; f < 8; f++) acc[i][f] = 0.f;

    int e = s0;
    for (; e + 7 < s1; e += 8) {
#pragma unroll
        for (int i = 0; i < 2; i++) {
            int c = g_csr[e + 4 * i + quarter];
            uint4 r = *(const uint4*)&hin[(size_t)c * 64 + fo];
            float2 f0 = __bfloat1622float2(*(__nv_bfloat162*)&r.x);
            float2 f1 = __bfloat1622float2(*(__nv_bfloat162*)&r.y);
            float2 f2 = __bfloat1622float2(*(__nv_bfloat162*)&r.z);
            float2 f3 = __bfloat1622float2(*(__nv_bfloat162*)&r.w);
            acc[i][0] += f0.x; acc[i][1] += f0.y;
            acc[i][2] += f1.x; acc[i][3] += f1.y;
            acc[i][4] += f2.x; acc[i][5] += f2.y;
            acc[i][6] += f3.x; acc[i][7] += f3.y;
        }
    }
    for (; e + 3 < s1; e += 4) {
        int c = g_csr[e + quarter];
        uint4 r = *(const uint4*)&hin[(size_t)c * 64 + fo];
        float2 f0 = __bfloat1622float2(*(__nv_bfloat162*)&r.x);
        float2 f1 = __bfloat1622float2(*(__nv_bfloat162*)&r.y);
        float2 f2 = __bfloat1622float2(*(__nv_bfloat162*)&r.z);
        float2 f3 = __bfloat1622float2(*(__nv_bfloat162*)&r.w);
        acc[0][0] += f0.x; acc[0][1] += f0.y;
        acc[0][2] += f1.x; acc[0][3] += f1.y;
        acc[0][4] += f2.x; acc[0][5] += f2.y;
        acc[0][6] += f3.x; acc[0][7] += f3.y;
    }
    if (e < s1) {                          // 1..3 remaining edges
        int rem = s1 - e;
        if (quarter < rem) {
            int c = g_csr[e + quarter];
            uint4 r = *(const uint4*)&hin[(size_t)c * 64 + fo];
            float2 f0 = __bfloat1622float2(*(__nv_bfloat162*)&r.x);
            float2 f1 = __bfloat1622float2(*(__nv_bfloat162*)&r.y);
            float2 f2 = __bfloat1622float2(*(__nv_bfloat162*)&r.z);
            float2 f3 = __bfloat1622float2(*(__nv_bfloat162*)&r.w);
            acc[1][0] += f0.x; acc[1][1] += f0.y;
            acc[1][2] += f1.x; acc[1][3] += f1.y;
            acc[1][4] += f2.x; acc[1][5] += f2.y;
            acc[1][6] += f3.x; acc[1][7] += f3.y;
        }
    }

    float v[8];
    float nd = g_ndst[node];
#pragma unroll
    for (int f = 0; f < 8; f++) {
        float t = acc[0][f] + acc[1][f];
        t += __shfl_xor_sync(0xFFFFFFFFu, t, 8);
        t += __shfl_xor_sync(0xFFFFFFFFu, t, 16);
        v[f] = t * nd + bias[fo + f];
    }

    // softmax over 64 vals = 8 lanes (lane&7 groups) x 8 local
    float m = v[0];
#pragma unroll
    for (int f = 1; f < 8; f++) m = fmaxf(m, v[f]);
#pragma unroll
    for (int off = 4; off > 0; off >>= 1)
        m = fmaxf(m, __shfl_xor_sync(0xFFFFFFFFu, m, off));
    float s = 0.f;
    float ev[8];
#pragma unroll
    for (int f = 0; f < 8; f++) { ev[f] = __expf(v[f] - m); s += ev[f]; }
#pragma unroll
    for (int off = 4; off > 0; off >>= 1)
        s += __shfl_xor_sync(0xFFFFFFFFu, s, off);
    float inv = 1.0f / s;

    if (quarter == 0) {                    // lanes 0..7 write 8 fp32 each
        float4 o0 = make_float4(ev[0] * inv, ev[1] * inv, ev[2] * inv, ev[3] * inv);
        float4 o1 = make_float4(ev[4] * inv, ev[5] * inv, ev[6] * inv, ev[7] * inv);
        *(float4*)&out[(size_t)node * 64 + fo] = o0;
        *(float4*)&out[(size_t)node * 64 + fo + 4] = o1;
    }
}

// ---------------- launch -----------------------------------------------------
extern "C" void kernel_launch(void* const* d_in, const int* in_sizes, int n_in,
                              void* d_out, int out_size) {
    const float* x   = (const float*)d_in[0];
    const int*   src = (const int*)d_in[1];    // int32: JAX x64 disabled
    const int*   dst = (const int*)d_in[2];
    const float* W0  = (const float*)d_in[3];
    const float* b0  = (const float*)d_in[4];
    const float* W1  = (const float*)d_in[5];
    const float* b1  = (const float*)d_in[6];
    const float* W2  = (const float*)d_in[7];
    const float* b2  = (const float*)d_in[8];
    float* out = (float*)d_out;

    const int nblk = (NN + 255) / 256;
    const int eblk = (EE + 255) / 256;
    const int sblk = (NN + 1023) / 1024;   // 98

    // graph preprocessing
    k_zero_deg<<<nblk, 256>>>();
    k_count<<<eblk, 256>>>(src, dst);
    k_scan1<<<sblk, 256>>>();
    k_scan2<<<1, 128>>>(sblk);
    k_scan3<<<nblk, 256>>>();
    k_scatter<<<eblk, 256>>>(src, dst);

    const int aggblk  = (NN * 32 + 255) / 256;   // 12500
    const int gemmblk = (NN + 127) / 128;        // 782

    // layer 0: x @ W0 -> hA16 (nsrc-scaled) ; aggregate -> hB16
    k_gemm_bf<true, HID><<<gemmblk, 256>>>(x, W0, NN, F0);
    k_agg128<<<aggblk, 256>>>(b0);
    // layer 1: hB16 @ W1 -> hA16 ; aggregate -> hB16
    k_gemm_bf<false, HID><<<gemmblk, 256>>>(nullptr, W1, NN, HID);
    k_agg128<<<aggblk, 256>>>(b1);
    // layer 2: hB16 @ W2 -> hA16 ; aggregate + softmax -> out
    k_gemm_bf<false, NCLS><<<gemmblk, 256>>>(nullptr, W2, NN, HID);
    k_agg64_softmax<<<aggblk, 256>>>(out, b2);
}